// round 8
// baseline (speedup 1.0000x reference)
#include <cuda_runtime.h>

// ---------------- problem dims ----------------
constexpr int B_   = 8;
constexpr int IMG_ = 224;
constexpr int G_   = 14;
constexpr int N_   = 196;   // G*G patches
constexpr int PD_  = 256;   // 16*16 patch dim
constexpr int D_   = 128;
constexpr int DFF_ = 256;
constexpr int C_   = 1000;
constexpr int M_   = B_ * N_;   // 1568 token rows

constexpr float NEGBIG = -1e30f;

// ---------------- scratch ----------------
__device__ float g_h[M_ * D_];
__device__ float g_qkv[3 * M_ * D_];
__device__ float g_S[B_ * N_ * N_];
__device__ float g_ff[M_ * DFF_];
__device__ float g_m[M_];
__device__ float g_pool[B_ * D_];

// epilogue modes
enum {
    EPI_STORE = 0,       // plain store
    EPI_POS_M = 1,       // v = acc + pos[(r%196)*ldo+cc]; also write rowmax -> mout
    EPI_SUBROW = 2,      // v = acc - aux[r]
    EPI_SUBROW_TAU = 3,  // v = max(acc - aux[r], tau[0])
    EPI_RESID_M = 4      // v = max(O_old, acc - rowmax(acc)); write rowmax(v) -> mout
};                       // (EPI_POS_M / EPI_RESID_M require BN == Nout == 128)

// ---------------- tropical GEMM (TM=1, TN=4) ----------------
// out[r, n] = max_k ( A[r, k] + W[n*wN + k*wK] )  (+ epilogue)
// One warp owns one output row (BM = warps). BN = 128 cols per block.
template <int BM, int BK, int EPI, bool PATCH, bool KCONTIG>
__global__ void __launch_bounds__(BM * 32)
trop_gemm(const float* __restrict__ A, int lda, long sA,
          const float* __restrict__ W0, const float* __restrict__ W1,
          const float* __restrict__ W2, int wN, int wK, long sW,
          float* __restrict__ O, int ldo, long sO,
          int M, int Nout, int K, long sM,
          const float* __restrict__ aux, float* __restrict__ mout,
          const float* __restrict__ tau) {
    constexpr int BN = 128;
    constexpr int TN = 4;
    constexpr int THREADS = BM * 32;
    static_assert(BK % 4 == 0, "");
    constexpr int VA = BM * BK / 4;           // float4 tiles of A
    constexpr int VB = BN * BK / 4;           // float4 tiles of B
    constexpr int ITA = (VA + THREADS - 1) / THREADS;
    constexpr int ITB = (VB + THREADS - 1) / THREADS;

    // As: row-major per output row -> warp reads its row via broadcast LDS.128
    __shared__ __align__(16) float As[2][BM][BK + 4];
    __shared__ __align__(16) float Bs[2][BK][BN + 4];

    const int z = blockIdx.z;
    A += (long)z * sA;
    O += (long)z * sO;
    const float* W;
    if (W1) W = (z == 0) ? W0 : (z == 1) ? W1 : W2;
    else    W = W0 + (long)z * sW;
    if (aux)  aux  += z * sM;
    if (mout) mout += z * sM;

    const int row0 = blockIdx.x * BM;
    const int n0 = blockIdx.y * BN;
    const int tid = threadIdx.x;
    const int tn = tid & 31;
    const int tm = tid >> 5;

    float4 apf[ITA], bpf[ITB];
    const int nchunks = (K + BK - 1) / BK;

    auto loadA = [&](int c) {
        #pragma unroll
        for (int i = 0; i < ITA; i++) {
            int t = tid + i * THREADS;
            if ((VA % THREADS) && t >= VA) break;
            int flat = t * 4;
            int kk = flat % BK, mm = flat / BK;
            int k = c * BK + kk, r = row0 + mm;
            float4 v;
            if (PATCH) {
                // A is raw image x: r -> (b, patch), k -> (pi, pj); pj contiguous
                int b = r / N_, n = r % N_;
                int gi = n / G_, gj = n % G_;
                int pi = k >> 4, pj = k & 15;
                v = *reinterpret_cast<const float4*>(
                    &A[((long)b * IMG_ + gi * 16 + pi) * IMG_ + gj * 16 + pj]);
            } else if (r < M) {
                if (k + 3 < K) {
                    v = *reinterpret_cast<const float4*>(&A[(long)r * lda + k]);
                } else {
                    v.x = (k + 0 < K) ? A[(long)r * lda + k + 0] : NEGBIG;
                    v.y = (k + 1 < K) ? A[(long)r * lda + k + 1] : NEGBIG;
                    v.z = (k + 2 < K) ? A[(long)r * lda + k + 2] : NEGBIG;
                    v.w = (k + 3 < K) ? A[(long)r * lda + k + 3] : NEGBIG;
                }
            } else {
                v = make_float4(NEGBIG, NEGBIG, NEGBIG, NEGBIG);
            }
            apf[i] = v;
        }
    };
    auto loadB = [&](int c) {
        #pragma unroll
        for (int i = 0; i < ITB; i++) {
            int t = tid + i * THREADS;
            if ((VB % THREADS) && t >= VB) break;
            int flat = t * 4;
            float4 v;
            if (KCONTIG) {
                // K contiguous in W (weights); call sites have K % BK == 0.
                int kk = flat % BK;
                int nn = n0 + flat / BK;
                int k = c * BK + kk;
                if (nn < Nout) {
                    v = *reinterpret_cast<const float4*>(&W[(long)nn * wN + k]);
                } else {
                    v = make_float4(NEGBIG, NEGBIG, NEGBIG, NEGBIG);
                }
            } else {
                // N contiguous (v operand of AV): vec along n.
                int n = flat % BN;
                int kk = flat / BN;
                int k = c * BK + kk;
                if (k < K) {
                    v = *reinterpret_cast<const float4*>(&W[(long)k * wK + n0 + n]);
                } else {
                    v = make_float4(NEGBIG, NEGBIG, NEGBIG, NEGBIG);
                }
            }
            bpf[i] = v;
        }
    };
    auto storeAB = [&](int s) {
        #pragma unroll
        for (int i = 0; i < ITA; i++) {
            int t = tid + i * THREADS;
            if ((VA % THREADS) && t >= VA) break;
            int flat = t * 4;
            int kk = flat % BK, mm = flat / BK;
            *reinterpret_cast<float4*>(&As[s][mm][kk]) = apf[i];   // STS.128
        }
        #pragma unroll
        for (int i = 0; i < ITB; i++) {
            int t = tid + i * THREADS;
            if ((VB % THREADS) && t >= VB) break;
            int flat = t * 4;
            if (KCONTIG) {
                int kk = flat % BK, n = flat / BK;
                Bs[s][kk + 0][n] = bpf[i].x;
                Bs[s][kk + 1][n] = bpf[i].y;
                Bs[s][kk + 2][n] = bpf[i].z;
                Bs[s][kk + 3][n] = bpf[i].w;
            } else {
                int n = flat % BN, kk = flat / BN;
                *reinterpret_cast<float4*>(&Bs[s][kk][n]) = bpf[i];
            }
        }
    };

    float acc[TN];
    #pragma unroll
    for (int j = 0; j < TN; j++) acc[j] = NEGBIG;

    loadA(0);
    loadB(0);
    storeAB(0);
    __syncthreads();

    for (int c = 0; c < nchunks; c++) {
        const int s = c & 1;
        const bool more = (c + 1 < nchunks);
        if (more) { loadA(c + 1); loadB(c + 1); }
        #pragma unroll
        for (int q = 0; q < BK / 4; q++) {
            float4 a4 = *reinterpret_cast<const float4*>(&As[s][tm][q * 4]);  // broadcast
            const float av[4] = {a4.x, a4.y, a4.z, a4.w};
            #pragma unroll
            for (int u = 0; u < 4; u++) {
                float4 b = *reinterpret_cast<const float4*>(&Bs[s][q * 4 + u][tn * TN]);
                acc[0] = fmaxf(acc[0], av[u] + b.x);
                acc[1] = fmaxf(acc[1], av[u] + b.y);
                acc[2] = fmaxf(acc[2], av[u] + b.z);
                acc[3] = fmaxf(acc[3], av[u] + b.w);
            }
        }
        if (more) {
            storeAB(s ^ 1);
            __syncthreads();
        }
    }

    // ---- epilogue ----
    const int r = row0 + tm;
    if (r >= M) return;

    float v[TN];
    if (EPI == EPI_RESID_M) {
        float rmax = fmaxf(fmaxf(acc[0], acc[1]), fmaxf(acc[2], acc[3]));
        #pragma unroll
        for (int off = 16; off; off >>= 1)
            rmax = fmaxf(rmax, __shfl_xor_sync(0xffffffffu, rmax, off));
        #pragma unroll
        for (int j = 0; j < TN; j++) {
            int cc = n0 + tn * TN + j;
            v[j] = fmaxf(O[(long)r * ldo + cc], acc[j] - rmax);
        }
    } else if (EPI == EPI_POS_M) {
        #pragma unroll
        for (int j = 0; j < TN; j++) {
            int cc = n0 + tn * TN + j;
            v[j] = acc[j] + aux[(r % N_) * ldo + cc];
        }
    } else {
        float sub = 0.f, tval = 0.f;
        if (EPI == EPI_SUBROW || EPI == EPI_SUBROW_TAU) sub = aux[r];
        if (EPI == EPI_SUBROW_TAU) tval = tau[0];
        #pragma unroll
        for (int j = 0; j < TN; j++) {
            float t = acc[j];
            if (EPI == EPI_SUBROW) t -= sub;
            else if (EPI == EPI_SUBROW_TAU) t = fmaxf(t - sub, tval);
            v[j] = t;
        }
    }

    #pragma unroll
    for (int j = 0; j < TN; j++) {
        int cc = n0 + tn * TN + j;
        if (cc < Nout) O[(long)r * ldo + cc] = v[j];
    }

    if (EPI == EPI_RESID_M || EPI == EPI_POS_M) {
        float nm = fmaxf(fmaxf(v[0], v[1]), fmaxf(v[2], v[3]));
        #pragma unroll
        for (int off = 16; off; off >>= 1)
            nm = fmaxf(nm, __shfl_xor_sync(0xffffffffu, nm, off));
        if (tn == 0) mout[r] = nm;
    }
}

// ---------------- tropical global pool over patches ----------------
__global__ void pool_kernel(const float* __restrict__ h, float* __restrict__ pool) {
    int idx = blockIdx.x * blockDim.x + threadIdx.x;
    if (idx >= B_ * D_) return;
    int d = idx % D_, b = idx / D_;
    float v = NEGBIG;
    for (int n = 0; n < N_; n++) v = fmaxf(v, h[((long)b * N_ + n) * D_ + d]);
    pool[idx] = v;
}

// ---------------- head ----------------
__global__ void head_kernel(const float* __restrict__ pool, const float* __restrict__ W,
                            const float* __restrict__ scale, float* __restrict__ out) {
    int gw = (blockIdx.x * blockDim.x + threadIdx.x) >> 5;
    int lane = threadIdx.x & 31;
    if (gw >= B_ * C_) return;
    int c = gw % C_, b = gw / C_;
    float v = NEGBIG;
    #pragma unroll
    for (int i = 0; i < 4; i++) {
        int d = lane + i * 32;
        v = fmaxf(v, pool[b * D_ + d] + W[(long)c * D_ + d]);
    }
    #pragma unroll
    for (int off = 16; off; off >>= 1) v = fmaxf(v, __shfl_xor_sync(0xffffffffu, v, off));
    if (lane == 0) out[gw] = v * scale[0];
}

// ---------------- host ----------------
extern "C" void kernel_launch(void* const* d_in, const int* in_sizes, int n_in,
                              void* d_out, int out_size) {
    const float* x       = (const float*)d_in[0];
    const float* embed_W = (const float*)d_in[1];
    const float* pos     = (const float*)d_in[2];
    const float* qW[2]   = {(const float*)d_in[3],  (const float*)d_in[9]};
    const float* kW[2]   = {(const float*)d_in[4],  (const float*)d_in[10]};
    const float* vW[2]   = {(const float*)d_in[5],  (const float*)d_in[11]};
    const float* f1W[2]  = {(const float*)d_in[6],  (const float*)d_in[12]};
    const float* f2W[2]  = {(const float*)d_in[7],  (const float*)d_in[13]};
    const float* tau[2]  = {(const float*)d_in[8],  (const float*)d_in[14]};
    const float* headW   = (const float*)d_in[15];
    const float* lscale  = (const float*)d_in[16];
    float* out = (float*)d_out;

    float *p_h, *p_qkv, *p_S, *p_ff, *p_m, *p_pool;
    cudaGetSymbolAddress((void**)&p_h, g_h);
    cudaGetSymbolAddress((void**)&p_qkv, g_qkv);
    cudaGetSymbolAddress((void**)&p_S, g_S);
    cudaGetSymbolAddress((void**)&p_ff, g_ff);
    cudaGetSymbolAddress((void**)&p_m, g_m);
    cudaGetSymbolAddress((void**)&p_pool, g_pool);

    const long tokD = (long)N_ * D_;
    const long qkvS = (long)M_ * D_;

    // embed (patchify fused): h = tropmm(patches, embed_W) + pos; m = rowmax(h)
    trop_gemm<8, 32, EPI_POS_M, true, true><<<dim3(196, 1, 1), 256>>>(
        x, 0, 0, embed_W, nullptr, nullptr, PD_, 1, 0,
        p_h, D_, 0, M_, D_, PD_, 0, pos, p_m, nullptr);

    for (int l = 0; l < 2; l++) {
        // q/k/v = tropmm(h, W) - m  (588 blocks x 8 warps = 4704 warps)
        trop_gemm<8, 32, EPI_SUBROW, false, true><<<dim3(196, 1, 3), 256>>>(
            p_h, D_, 0, qW[l], kW[l], vW[l], D_, 1, 0,
            p_qkv, D_, qkvS, M_, D_, D_, 0, p_m, nullptr, nullptr);

        // S[b,i,j] = max_d(q_id + k_jd)  (snorm absorbed by later pnorm) — 400 blocks
        trop_gemm<8, 32, EPI_STORE, false, true><<<dim3(25, 2, 8), 256>>>(
            p_qkv, D_, tokD, p_qkv + qkvS, nullptr, nullptr, D_, 1, tokD,
            p_S, N_, (long)N_ * N_, N_, N_, D_, 0, nullptr, nullptr, nullptr);

        // h = max(h, pnorm(max_j(S + v)));  m = rowmax(h) — 200 blocks
        trop_gemm<8, 32, EPI_RESID_M, false, false><<<dim3(25, 1, 8), 256>>>(
            p_S, N_, (long)N_ * N_, p_qkv + 2 * qkvS, nullptr, nullptr, 1, D_, tokD,
            p_h, D_, tokD, N_, D_, N_, N_, nullptr, p_m, nullptr);

        // ff = max(tropmm(h, f1W) - m, tau) — 392 blocks
        trop_gemm<8, 32, EPI_SUBROW_TAU, false, true><<<dim3(196, 2, 1), 256>>>(
            p_h, D_, 0, f1W[l], nullptr, nullptr, D_, 1, 0,
            p_ff, DFF_, 0, M_, DFF_, D_, 0, p_m, nullptr, tau[l]);

        // h = max(h, pnorm(tropmm(ff, f2W)));  m = rowmax(h) — 196 blocks
        trop_gemm<8, 32, EPI_RESID_M, false, true><<<dim3(196, 1, 1), 256>>>(
            p_ff, DFF_, 0, f2W[l], nullptr, nullptr, DFF_, 1, 0,
            p_h, D_, 0, M_, D_, DFF_, 0, nullptr, p_m, nullptr);
    }

    pool_kernel<<<8, 128>>>(p_h, p_pool);
    head_kernel<<<1000, 256>>>(p_pool, headW, lscale, out);
}

// round 9
// speedup vs baseline: 1.2917x; 1.2917x over previous
#include <cuda_runtime.h>

// ---------------- problem dims ----------------
constexpr int B_   = 8;
constexpr int IMG_ = 224;
constexpr int G_   = 14;
constexpr int N_   = 196;   // G*G patches
constexpr int PD_  = 256;   // 16*16 patch dim
constexpr int D_   = 128;
constexpr int DFF_ = 256;
constexpr int C_   = 1000;
constexpr int M_   = B_ * N_;   // 1568 token rows

constexpr float NEGBIG = -1e30f;

// ---------------- scratch ----------------
__device__ float g_h[M_ * D_];
__device__ float g_qkv[3 * M_ * D_];
__device__ float g_S[B_ * N_ * N_];
__device__ float g_ff[M_ * DFF_];
__device__ float g_m[M_];
__device__ float g_pool[B_ * D_];

// epilogue modes
enum {
    EPI_STORE = 0,       // plain store
    EPI_POS_M = 1,       // v = acc + pos[(r%196)*ldo+cc]; also write rowmax -> mout
    EPI_SUBROW = 2,      // v = acc - aux[r]
    EPI_SUBROW_TAU = 3,  // v = max(acc - aux[r], tau[0])
    EPI_RESID_M = 4      // v = max(O_old, acc - rowmax(acc)); write rowmax(v) -> mout
};                       // (EPI_POS_M / EPI_RESID_M require BN == Nout == 128)

// ---------------- tropical GEMM ----------------
// out[r, n] = max_k ( A[r, k] + W[n*wN + k*wK] )  (+ epilogue)
// BN = 128, TN = 4 fixed: one warp spans the 128-col tile; TM rows per thread.
template <int BM, int TM, int EPI, bool PATCH, bool KCONTIG>
__global__ void __launch_bounds__((BM / TM) * 32)
trop_gemm(const float* __restrict__ A, int lda, long sA,
          const float* __restrict__ W0, const float* __restrict__ W1,
          const float* __restrict__ W2, int wN, int wK, long sW,
          float* __restrict__ O, int ldo, long sO,
          int M, int Nout, int K, long sM,
          const float* __restrict__ aux, float* __restrict__ mout,
          const float* __restrict__ tau) {
    constexpr int BN = 128;
    constexpr int TN = 4;
    constexpr int BK = 32;
    constexpr int THREADS = (BM / TM) * 32;
    constexpr int VA = BM * BK / 4;           // float4 tiles of A
    constexpr int VB = BN * BK / 4;           // float4 tiles of B
    constexpr int ITA = (VA + THREADS - 1) / THREADS;
    constexpr int ITB = (VB + THREADS - 1) / THREADS;

    // As row-major: STS.128 on store, broadcast LDS.128 on read
    __shared__ __align__(16) float As[2][BM][BK + 4];
    __shared__ __align__(16) float Bs[2][BK][BN + 4];

    const int z = blockIdx.z;
    A += (long)z * sA;
    O += (long)z * sO;
    const float* W;
    if (W1) W = (z == 0) ? W0 : (z == 1) ? W1 : W2;
    else    W = W0 + (long)z * sW;
    if (aux)  aux  += z * sM;
    if (mout) mout += z * sM;

    const int row0 = blockIdx.x * BM;
    const int n0 = blockIdx.y * BN;
    const int tid = threadIdx.x;
    const int tn = tid & 31;
    const int tm = tid >> 5;

    float4 apf[ITA], bpf[ITB];
    const int nchunks = (K + BK - 1) / BK;

    auto loadA = [&](int c) {
        #pragma unroll
        for (int i = 0; i < ITA; i++) {
            int t = tid + i * THREADS;
            if ((VA % THREADS) && t >= VA) break;
            int flat = t * 4;
            int kk = flat % BK, mm = flat / BK;
            int k = c * BK + kk, r = row0 + mm;
            float4 v;
            if (PATCH) {
                // A is raw image x: r -> (b, patch), k -> (pi, pj); pj contiguous
                int b = r / N_, n = r % N_;
                int gi = n / G_, gj = n % G_;
                int pi = k >> 4, pj = k & 15;
                v = *reinterpret_cast<const float4*>(
                    &A[((long)b * IMG_ + gi * 16 + pi) * IMG_ + gj * 16 + pj]);
            } else if (r < M) {
                if (k + 3 < K) {
                    v = *reinterpret_cast<const float4*>(&A[(long)r * lda + k]);
                } else {
                    v.x = (k + 0 < K) ? A[(long)r * lda + k + 0] : NEGBIG;
                    v.y = (k + 1 < K) ? A[(long)r * lda + k + 1] : NEGBIG;
                    v.z = (k + 2 < K) ? A[(long)r * lda + k + 2] : NEGBIG;
                    v.w = (k + 3 < K) ? A[(long)r * lda + k + 3] : NEGBIG;
                }
            } else {
                v = make_float4(NEGBIG, NEGBIG, NEGBIG, NEGBIG);
            }
            apf[i] = v;
        }
    };
    auto loadB = [&](int c) {
        #pragma unroll
        for (int i = 0; i < ITB; i++) {
            int t = tid + i * THREADS;
            if ((VB % THREADS) && t >= VB) break;
            int flat = t * 4;
            float4 v;
            if (KCONTIG) {
                // K contiguous in W (weights); KCONTIG call sites have K % BK == 0.
                int kk = flat % BK;
                int nn = n0 + flat / BK;
                int k = c * BK + kk;
                if (nn < Nout) {
                    v = *reinterpret_cast<const float4*>(&W[(long)nn * wN + k]);
                } else {
                    v = make_float4(NEGBIG, NEGBIG, NEGBIG, NEGBIG);
                }
            } else {
                // N contiguous (v operand of AV): vec along n; guard K tail.
                int n = flat % BN;
                int kk = flat / BN;
                int k = c * BK + kk;
                if (k < K) {
                    v = *reinterpret_cast<const float4*>(&W[(long)k * wK + n0 + n]);
                } else {
                    v = make_float4(NEGBIG, NEGBIG, NEGBIG, NEGBIG);
                }
            }
            bpf[i] = v;
        }
    };
    auto storeAB = [&](int s) {
        #pragma unroll
        for (int i = 0; i < ITA; i++) {
            int t = tid + i * THREADS;
            if ((VA % THREADS) && t >= VA) break;
            int flat = t * 4;
            int kk = flat % BK, mm = flat / BK;
            *reinterpret_cast<float4*>(&As[s][mm][kk]) = apf[i];   // STS.128
        }
        #pragma unroll
        for (int i = 0; i < ITB; i++) {
            int t = tid + i * THREADS;
            if ((VB % THREADS) && t >= VB) break;
            int flat = t * 4;
            if (KCONTIG) {
                int kk = flat % BK, n = flat / BK;
                Bs[s][kk + 0][n] = bpf[i].x;
                Bs[s][kk + 1][n] = bpf[i].y;
                Bs[s][kk + 2][n] = bpf[i].z;
                Bs[s][kk + 3][n] = bpf[i].w;
            } else {
                int n = flat % BN, kk = flat / BN;
                *reinterpret_cast<float4*>(&Bs[s][kk][n]) = bpf[i];
            }
        }
    };

    float acc[TM][TN];
    #pragma unroll
    for (int i = 0; i < TM; i++)
        #pragma unroll
        for (int j = 0; j < TN; j++) acc[i][j] = NEGBIG;

    // Early read of old output rows for the residual epilogue (hide LDG latency)
    float oldv[TM][TN];
    if (EPI == EPI_RESID_M) {
        #pragma unroll
        for (int i = 0; i < TM; i++) {
            int r = row0 + tm * TM + i;
            if (r < M) {
                float4 o4 = *reinterpret_cast<const float4*>(&O[(long)r * ldo + n0 + tn * TN]);
                oldv[i][0] = o4.x; oldv[i][1] = o4.y; oldv[i][2] = o4.z; oldv[i][3] = o4.w;
            }
        }
    }

    loadA(0);
    loadB(0);
    storeAB(0);
    __syncthreads();

    for (int c = 0; c < nchunks; c++) {
        const int s = c & 1;
        const bool more = (c + 1 < nchunks);
        if (more) { loadA(c + 1); loadB(c + 1); }
        #pragma unroll
        for (int q = 0; q < BK / 4; q++) {
            float4 a4[TM];
            #pragma unroll
            for (int i = 0; i < TM; i++)
                a4[i] = *reinterpret_cast<const float4*>(&As[s][tm * TM + i][q * 4]);
            #pragma unroll
            for (int u = 0; u < 4; u++) {
                float4 b = *reinterpret_cast<const float4*>(&Bs[s][q * 4 + u][tn * TN]);
                #pragma unroll
                for (int i = 0; i < TM; i++) {
                    float av = (u == 0) ? a4[i].x : (u == 1) ? a4[i].y
                             : (u == 2) ? a4[i].z : a4[i].w;
                    acc[i][0] = fmaxf(acc[i][0], av + b.x);
                    acc[i][1] = fmaxf(acc[i][1], av + b.y);
                    acc[i][2] = fmaxf(acc[i][2], av + b.z);
                    acc[i][3] = fmaxf(acc[i][3], av + b.w);
                }
            }
        }
        if (more) {
            storeAB(s ^ 1);
            __syncthreads();
        }
    }

    // ---- epilogue ----
    float tval = 0.f;
    if (EPI == EPI_SUBROW_TAU) tval = tau[0];

    #pragma unroll
    for (int i = 0; i < TM; i++) {
        int r = row0 + tm * TM + i;
        if (r >= M) continue;
        float sub = 0.f;
        if (EPI == EPI_SUBROW || EPI == EPI_SUBROW_TAU) sub = aux[r];

        float v[TN];
        if (EPI == EPI_RESID_M) {
            float rmax = fmaxf(fmaxf(acc[i][0], acc[i][1]), fmaxf(acc[i][2], acc[i][3]));
            #pragma unroll
            for (int off = 16; off; off >>= 1)
                rmax = fmaxf(rmax, __shfl_xor_sync(0xffffffffu, rmax, off));
            #pragma unroll
            for (int j = 0; j < TN; j++)
                v[j] = fmaxf(oldv[i][j], acc[i][j] - rmax);
        } else if (EPI == EPI_POS_M) {
            #pragma unroll
            for (int j = 0; j < TN; j++) {
                int cc = n0 + tn * TN + j;
                v[j] = acc[i][j] + aux[(r % N_) * ldo + cc];
            }
        } else {
            #pragma unroll
            for (int j = 0; j < TN; j++) {
                float t = acc[i][j];
                if (EPI == EPI_SUBROW) t -= sub;
                else if (EPI == EPI_SUBROW_TAU) t = fmaxf(t - sub, tval);
                v[j] = t;
            }
        }

        #pragma unroll
        for (int j = 0; j < TN; j++) {
            int cc = n0 + tn * TN + j;
            if (cc < Nout) O[(long)r * ldo + cc] = v[j];
        }

        if (EPI == EPI_RESID_M || EPI == EPI_POS_M) {
            float nm = fmaxf(fmaxf(v[0], v[1]), fmaxf(v[2], v[3]));
            #pragma unroll
            for (int off = 16; off; off >>= 1)
                nm = fmaxf(nm, __shfl_xor_sync(0xffffffffu, nm, off));
            if (tn == 0) mout[r] = nm;
        }
    }
}

// ---------------- tropical global pool over patches ----------------
__global__ void pool_kernel(const float* __restrict__ h, float* __restrict__ pool) {
    int idx = blockIdx.x * blockDim.x + threadIdx.x;
    if (idx >= B_ * D_) return;
    int d = idx % D_, b = idx / D_;
    float v = NEGBIG;
    for (int n = 0; n < N_; n++) v = fmaxf(v, h[((long)b * N_ + n) * D_ + d]);
    pool[idx] = v;
}

// ---------------- head ----------------
__global__ void head_kernel(const float* __restrict__ pool, const float* __restrict__ W,
                            const float* __restrict__ scale, float* __restrict__ out) {
    int gw = (blockIdx.x * blockDim.x + threadIdx.x) >> 5;
    int lane = threadIdx.x & 31;
    if (gw >= B_ * C_) return;
    int c = gw % C_, b = gw / C_;
    float v = NEGBIG;
    #pragma unroll
    for (int i = 0; i < 4; i++) {
        int d = lane + i * 32;
        v = fmaxf(v, pool[b * D_ + d] + W[(long)c * D_ + d]);
    }
    #pragma unroll
    for (int off = 16; off; off >>= 1) v = fmaxf(v, __shfl_xor_sync(0xffffffffu, v, off));
    if (lane == 0) out[gw] = v * scale[0];
}

// ---------------- host ----------------
extern "C" void kernel_launch(void* const* d_in, const int* in_sizes, int n_in,
                              void* d_out, int out_size) {
    const float* x       = (const float*)d_in[0];
    const float* embed_W = (const float*)d_in[1];
    const float* pos     = (const float*)d_in[2];
    const float* qW[2]   = {(const float*)d_in[3],  (const float*)d_in[9]};
    const float* kW[2]   = {(const float*)d_in[4],  (const float*)d_in[10]};
    const float* vW[2]   = {(const float*)d_in[5],  (const float*)d_in[11]};
    const float* f1W[2]  = {(const float*)d_in[6],  (const float*)d_in[12]};
    const float* f2W[2]  = {(const float*)d_in[7],  (const float*)d_in[13]};
    const float* tau[2]  = {(const float*)d_in[8],  (const float*)d_in[14]};
    const float* headW   = (const float*)d_in[15];
    const float* lscale  = (const float*)d_in[16];
    float* out = (float*)d_out;

    float *p_h, *p_qkv, *p_S, *p_ff, *p_m, *p_pool;
    cudaGetSymbolAddress((void**)&p_h, g_h);
    cudaGetSymbolAddress((void**)&p_qkv, g_qkv);
    cudaGetSymbolAddress((void**)&p_S, g_S);
    cudaGetSymbolAddress((void**)&p_ff, g_ff);
    cudaGetSymbolAddress((void**)&p_m, g_m);
    cudaGetSymbolAddress((void**)&p_pool, g_pool);

    const long tokD = (long)N_ * D_;
    const long qkvS = (long)M_ * D_;

    // embed (patchify fused): h = tropmm(patches, embed_W) + pos; m = rowmax(h)
    // TM=2: 196 blocks x 4 warps
    trop_gemm<8, 2, EPI_POS_M, true, true><<<dim3(196, 1, 1), 128>>>(
        x, 0, 0, embed_W, nullptr, nullptr, PD_, 1, 0,
        p_h, D_, 0, M_, D_, PD_, 0, pos, p_m, nullptr);

    for (int l = 0; l < 2; l++) {
        // q/k/v = tropmm(h, W) - m  (TM=4: 294 blocks x 4 warps = 1176 warps)
        trop_gemm<16, 4, EPI_SUBROW, false, true><<<dim3(98, 1, 3), 128>>>(
            p_h, D_, 0, qW[l], kW[l], vW[l], D_, 1, 0,
            p_qkv, D_, qkvS, M_, D_, D_, 0, p_m, nullptr, nullptr);

        // S[b,i,j] = max_d(q_id + k_jd)  (TM=4: 208 blocks)
        trop_gemm<16, 4, EPI_STORE, false, true><<<dim3(13, 2, 8), 128>>>(
            p_qkv, D_, tokD, p_qkv + qkvS, nullptr, nullptr, D_, 1, tokD,
            p_S, N_, (long)N_ * N_, N_, N_, D_, 0, nullptr, nullptr, nullptr);

        // h = max(h, pnorm(max_j(S + v)));  m = rowmax(h)  (TM=2: 200 blocks)
        trop_gemm<8, 2, EPI_RESID_M, false, false><<<dim3(25, 1, 8), 128>>>(
            p_S, N_, (long)N_ * N_, p_qkv + 2 * qkvS, nullptr, nullptr, 1, D_, tokD,
            p_h, D_, tokD, N_, D_, N_, N_, nullptr, p_m, nullptr);

        // ff = max(tropmm(h, f1W) - m, tau)  (TM=4: 196 blocks)
        trop_gemm<16, 4, EPI_SUBROW_TAU, false, true><<<dim3(98, 2, 1), 128>>>(
            p_h, D_, 0, f1W[l], nullptr, nullptr, D_, 1, 0,
            p_ff, DFF_, 0, M_, DFF_, D_, 0, p_m, nullptr, tau[l]);

        // h = max(h, pnorm(tropmm(ff, f2W)));  m = rowmax(h)  (TM=2: 196 blocks)
        trop_gemm<8, 2, EPI_RESID_M, false, true><<<dim3(196, 1, 1), 128>>>(
            p_ff, DFF_, 0, f2W[l], nullptr, nullptr, DFF_, 1, 0,
            p_h, D_, 0, M_, D_, DFF_, 0, nullptr, p_m, nullptr);
    }

    pool_kernel<<<8, 128>>>(p_h, p_pool);
    head_kernel<<<1000, 256>>>(p_pool, headW, lscale, out);
}